// round 4
// baseline (speedup 1.0000x reference)
#include <cuda_runtime.h>
#include <math.h>

#define HW      16384
#define BATCH   4
#define MTOK    256
#define HD      256
#define INNER   128
#define DH      64

#define TWO_PI 6.2831853071795864769f

typedef unsigned long long u64;

// ---- packed f32x2 helpers (sm_100+) ---------------------------------------
__device__ __forceinline__ u64 pack1(float v) {
    u64 r; asm("mov.b64 %0, {%1, %2};" : "=l"(r) : "f"(v), "f"(v)); return r;
}
__device__ __forceinline__ u64 ffma2(u64 a, u64 b, u64 c) {
    u64 d; asm("fma.rn.f32x2 %0, %1, %2, %3;" : "=l"(d) : "l"(a), "l"(b), "l"(c)); return d;
}
__device__ __forceinline__ u64 fmul2(u64 a, u64 b) {
    u64 d; asm("mul.rn.f32x2 %0, %1, %2;" : "=l"(d) : "l"(a), "l"(b)); return d;
}
__device__ __forceinline__ u64 fadd2(u64 a, u64 b) {
    u64 d; asm("add.rn.f32x2 %0, %1, %2;" : "=l"(d) : "l"(a), "l"(b)); return d;
}
__device__ __forceinline__ float2 unpack2(u64 v) {
    float2 f; asm("mov.b64 {%0, %1}, %2;" : "=f"(f.x), "=f"(f.y) : "l"(v)); return f;
}

// ---- cp.async helpers ------------------------------------------------------
__device__ __forceinline__ void cpa16(float* dst, const float* src) {
    unsigned d = (unsigned)__cvta_generic_to_shared(dst);
    asm volatile("cp.async.ca.shared.global [%0], [%1], 16;" :: "r"(d), "l"(src));
}
#define CPA_COMMIT() asm volatile("cp.async.commit_group;" ::: "memory")
#define CPA_WAIT0()  asm volatile("cp.async.wait_group 0;"  ::: "memory")

// ---------------- scratch ---------------------------------------------------
__device__ float g_q  [HW * INNER];
__device__ float g_h0 [HW * HD];
__device__ float g_h1 [HW * HD];
__device__ float g_t  [HW];
__device__ float g_k  [BATCH * 2 * MTOK * DH];
__device__ float g_v  [BATCH * 2 * MTOK * DH];
__device__ float g_o  [BATCH * HW * INNER];

// ============================================================================
// K1: grid-shared features. 16 rows / block, 256 threads.
// ============================================================================
__global__ void k1_grid(const float* __restrict__ coords,
                        const float* __restrict__ Bq,
                        const float* __restrict__ Bl0,
                        const float* __restrict__ Bl1,
                        const float* __restrict__ qW,  const float* __restrict__ qb,
                        const float* __restrict__ toqW,
                        const float* __restrict__ bwW0, const float* __restrict__ bwb0,
                        const float* __restrict__ bwW1, const float* __restrict__ bwb1)
{
    __shared__ float four[3][16][64];
    __shared__ float xq[16][256];
    const int tid  = threadIdx.x;
    const int base = blockIdx.x * 16;

    for (int it = tid; it < 3 * 16 * 32; it += 256) {
        int mat = it >> 9;
        int rem = it & 511;
        int r   = rem >> 5;
        int i   = rem & 31;
        float x = coords[(base + r) * 2 + 0];
        float y = coords[(base + r) * 2 + 1];
        const float* Bm = (mat == 0) ? Bq : (mat == 1 ? Bl0 : Bl1);
        float proj = TWO_PI * (x * Bm[i * 2] + y * Bm[i * 2 + 1]);
        float s, c;
        sincosf(proj, &s, &c);
        four[mat][r][i]      = c;
        four[mat][r][i + 32] = s;
    }
    if (tid < 16) {
        float x = coords[(base + tid) * 2 + 0];
        float y = coords[(base + tid) * 2 + 1];
        int row = (int)(x * 16.0f); row = min(max(row, 0), 15);
        int col = (int)(y * 16.0f); col = min(max(col, 0), 15);
        g_t[base + tid] = (float)(row * 16 + col) * (1.0f / 256.0f);
    }
    __syncthreads();

    {
        const int j = tid;
        float acc[16];
#pragma unroll
        for (int r = 0; r < 16; r++) acc[r] = 0.f;
        for (int k = 0; k < 64; k++) {
            float w = qW[k * 256 + j];
#pragma unroll
            for (int r = 0; r < 16; r++) acc[r] = fmaf(four[0][r][k], w, acc[r]);
        }
        float b = qb[j];
#pragma unroll
        for (int r = 0; r < 16; r++) xq[r][j] = fmaxf(acc[r] + b, 0.f);
    }
    __syncthreads();

    {
        const int j    = tid & 127;
        const int half = tid >> 7;
        float acc[8];
#pragma unroll
        for (int r = 0; r < 8; r++) acc[r] = 0.f;
        for (int k = 0; k < 256; k++) {
            float w = toqW[k * 128 + j];
#pragma unroll
            for (int r = 0; r < 8; r++) acc[r] = fmaf(xq[half * 8 + r][k], w, acc[r]);
        }
#pragma unroll
        for (int r = 0; r < 8; r++) g_q[(base + half * 8 + r) * 128 + j] = acc[r];
    }

    {
        const int j = tid;
        float a0[16], a1[16];
#pragma unroll
        for (int r = 0; r < 16; r++) { a0[r] = 0.f; a1[r] = 0.f; }
        for (int k = 0; k < 64; k++) {
            float w0 = bwW0[k * 256 + j];
            float w1 = bwW1[k * 256 + j];
#pragma unroll
            for (int r = 0; r < 16; r++) {
                a0[r] = fmaf(four[1][r][k], w0, a0[r]);
                a1[r] = fmaf(four[2][r][k], w1, a1[r]);
            }
        }
        float b0 = bwb0[j], b1 = bwb1[j];
#pragma unroll
        for (int r = 0; r < 16; r++) {
            g_h0[(base + r) * 256 + j] = fmaxf(a0[r] + b0, 0.f);
            g_h1[(base + r) * 256 + j] = fmaxf(a1[r] + b1, 0.f);
        }
    }
}

// ============================================================================
// K2: kv = tokens @ tokvW -> per-head k / v.
// ============================================================================
__global__ void k2_kv(const float* __restrict__ tokens,
                      const float* __restrict__ tokvW)
{
    __shared__ float tok[16][256];
    const int tile = blockIdx.x;
    const int b    = blockIdx.y;
    const int tid  = threadIdx.x;

    const float* tb = tokens + (b * MTOK + tile * 16) * 256;
    for (int i = tid; i < 16 * 256; i += 256) tok[i >> 8][i & 255] = tb[i];
    __syncthreads();

    const int j = tid;
    float acc[16];
#pragma unroll
    for (int r = 0; r < 16; r++) acc[r] = 0.f;
    for (int k = 0; k < 256; k++) {
        float w = tokvW[k * 256 + j];
#pragma unroll
        for (int r = 0; r < 16; r++) acc[r] = fmaf(tok[r][k], w, acc[r]);
    }
#pragma unroll
    for (int r = 0; r < 16; r++) {
        int m = tile * 16 + r;
        if (j < 128) {
            int h = j >> 6, d = j & 63;
            g_k[((b * 2 + h) * MTOK + m) * DH + d] = acc[r];
        } else {
            int j2 = j - 128;
            int h = j2 >> 6, d = j2 & 63;
            g_v[((b * 2 + h) * MTOK + m) * DH + d] = acc[r];
        }
    }
}

// ============================================================================
// K3 v2: attention. 512 threads/block; 2 lanes per query row (32 dims each).
// k,v SMEM-resident (128 KB). shfl_xor combines the QK partial.
// ============================================================================
__global__ void __launch_bounds__(512) k3_attn()
{
    extern __shared__ float sm[];
    float* ks = sm;                 // [256][64]
    float* vs = sm + MTOK * DH;

    const int h   = blockIdx.y;
    const int b   = blockIdx.z;
    const int tid = threadIdx.x;

    const float* kg = g_k + (b * 2 + h) * MTOK * DH;
    const float* vg = g_v + (b * 2 + h) * MTOK * DH;
    for (int i = tid * 4; i < MTOK * DH; i += 512 * 4) {
        *(float4*)&ks[i] = *(const float4*)&kg[i];
        *(float4*)&vs[i] = *(const float4*)&vg[i];
    }
    __syncthreads();

    const int pair = tid & 1;               // which 32-dim half
    const int row  = blockIdx.x * 256 + (tid >> 1);
    const int dofs = pair * 32;

    u64 q2[16];
    {
        const ulonglong2* qp = (const ulonglong2*)(g_q + row * 128 + h * 64 + dofs);
#pragma unroll
        for (int i = 0; i < 8; i++) { ulonglong2 t = qp[i]; q2[2*i] = t.x; q2[2*i+1] = t.y; }
    }
    const float tt = g_t[row];

    u64 acc[16];
#pragma unroll
    for (int i = 0; i < 16; i++) acc[i] = 0ULL;
    float Mx = -1e30f, S = 0.f;

    for (int m = 0; m < 256; m++) {
        const ulonglong2* kp = (const ulonglong2*)&ks[m * 64 + dofs];
        u64 sA = 0, sB = 0, sC = 0, sD = 0;
#pragma unroll
        for (int i = 0; i < 8; i += 2) {
            ulonglong2 k0 = kp[i];
            ulonglong2 k1 = kp[i + 1];
            sA = ffma2(q2[2*i    ], k0.x, sA);
            sB = ffma2(q2[2*i + 1], k0.y, sB);
            sC = ffma2(q2[2*i + 2], k1.x, sC);
            sD = ffma2(q2[2*i + 3], k1.y, sD);
        }
        float2 sf = unpack2(fadd2(fadd2(sA, sB), fadd2(sC, sD)));
        float part = sf.x + sf.y;
        part += __shfl_xor_sync(0xffffffffu, part, 1);
        float pos  = ((float)m + 0.5f) * (1.0f / 256.0f);
        float diff = tt - pos;
        float s = part * 0.125f - 10.0f * diff * diff;

        if (s > Mx) {
            float corr = __expf(Mx - s);
            S *= corr;
            u64 cp = pack1(corr);
#pragma unroll
            for (int i = 0; i < 16; i++) acc[i] = fmul2(acc[i], cp);
            Mx = s;
        }
        float p = __expf(s - Mx);
        S += p;
        u64 pp = pack1(p);
        const ulonglong2* vp = (const ulonglong2*)&vs[m * 64 + dofs];
#pragma unroll
        for (int i = 0; i < 8; i++) {
            ulonglong2 v0 = vp[i];
            acc[2*i    ] = ffma2(pp, v0.x, acc[2*i    ]);
            acc[2*i + 1] = ffma2(pp, v0.y, acc[2*i + 1]);
        }
    }

    float inv = 1.0f / S;
    float* og = g_o + ((size_t)b * HW + row) * 128 + h * 64 + dofs;
#pragma unroll
    for (int i = 0; i < 16; i++) {
        float2 f = unpack2(acc[i]);
        float2 o2; o2.x = f.x * inv; o2.y = f.y * inv;
        *(float2*)&og[2 * i] = o2;
    }
}

// ============================================================================
// K5 v4: fused MLP chain. 64 rows/block, 512 threads (16 warps), 4x8 tiles.
// Weights via cp.async double buffer, 32-k chunks. Sequential GEMM passes.
// ============================================================================
__device__ __forceinline__ void copy_chunk32(float* dst, const float* W, int k0, int tid)
{
#pragma unroll
    for (int it = 0; it < 4; it++) {
        int f  = it * 512 + tid;     // float4 id (2048 total = 32 rows x 64)
        int k  = f >> 6;
        int c4 = f & 63;
        cpa16(dst + k * 256 + c4 * 4, W + (k0 + k) * 256 + c4 * 4);
    }
}

__device__ __forceinline__ void gemm32(const float* sIn, int lda, int kbase,
                                       const float* wb, int r0, int c0, u64* a)
{
#pragma unroll
    for (int kk = 0; kk < 32; kk++) {
        const float* wr = wb + kk * 256;
        ulonglong2 wa = *(const ulonglong2*)(wr + c0);
        ulonglong2 wv = *(const ulonglong2*)(wr + c0 + 4);
#pragma unroll
        for (int r = 0; r < 4; r++) {
            u64 p = pack1(sIn[(r0 + r) * lda + kbase + kk]);
            a[r*4+0] = ffma2(p, wa.x, a[r*4+0]);
            a[r*4+1] = ffma2(p, wa.y, a[r*4+1]);
            a[r*4+2] = ffma2(p, wv.x, a[r*4+2]);
            a[r*4+3] = ffma2(p, wv.y, a[r*4+3]);
        }
    }
}

// run a full GEMM (K = nchunks*32) with double-buffered weights
__device__ __forceinline__ void gemm_pipe(const float* sIn, int lda, const float* W,
                                          float* sW, int nchunks, int tid,
                                          int r0, int c0, u64* a)
{
    copy_chunk32(sW, W, 0, tid);
    CPA_COMMIT(); CPA_WAIT0();
    __syncthreads();
    for (int c = 0; c < nchunks; c++) {
        if (c < nchunks - 1) { copy_chunk32(sW + ((c+1)&1)*8192, W, (c+1)*32, tid); CPA_COMMIT(); }
        gemm32(sIn, lda, c * 32, sW + (c&1)*8192, r0, c0, a);
        CPA_WAIT0();
        __syncthreads();
    }
}

__global__ void __launch_bounds__(512, 1) k5_v4(
    const float* __restrict__ tooW,  const float* __restrict__ toob,
    const float* __restrict__ modW0, const float* __restrict__ modb0,
    const float* __restrict__ modW1, const float* __restrict__ modb1,
    const float* __restrict__ hvW0,  const float* __restrict__ hvb0,
    const float* __restrict__ outW0, const float* __restrict__ outb0,
    const float* __restrict__ outW1, const float* __restrict__ outb1,
    float* __restrict__ out)
{
    extern __shared__ float smf[];
    float* sA = smf;              // 64x256 (o -> m0)
    float* sB = smf + 16384;      // 64x256 (mod -> x -> hv1)
    float* sW = smf + 32768;      // 2 x 8192 weight buffers (64 KB)

    const int tid  = threadIdx.x;
    const int warp = tid >> 5, lane = tid & 31;
    const int r0   = warp * 4;
    const int c0   = lane * 8;
    const int base = blockIdx.x * 64;
    const int hwb  = base & (HW - 1);

    // load o tile (64x128) into sA
    for (int i = tid * 4; i < 64 * 128; i += 2048)
        *(float4*)&sA[i] = *(const float4*)&g_o[(size_t)base * 128 + i];
    __syncthreads();

    u64 a[16];

    // ---- stage 0: mod = o @ tooW + toob  -> sB ----
#pragma unroll
    for (int i = 0; i < 16; i++) a[i] = 0ULL;
    gemm_pipe(sA, 128, tooW, sW, 4, tid, r0, c0, a);
    {
        ulonglong2 ba = *(const ulonglong2*)(toob + c0);
        ulonglong2 bb = *(const ulonglong2*)(toob + c0 + 4);
#pragma unroll
        for (int r = 0; r < 4; r++) {
            ulonglong2 o1, o2;
            o1.x = fadd2(a[r*4+0], ba.x); o1.y = fadd2(a[r*4+1], ba.y);
            o2.x = fadd2(a[r*4+2], bb.x); o2.y = fadd2(a[r*4+3], bb.y);
            *(ulonglong2*)&sB[(r0 + r) * 256 + c0]     = o1;
            *(ulonglong2*)&sB[(r0 + r) * 256 + c0 + 4] = o2;
        }
    }
    __syncthreads();

    // ---- stage 1a: m0 = relu(h0 + mod@modW0 + b)  -> sA ----
#pragma unroll
    for (int i = 0; i < 16; i++) a[i] = 0ULL;
    gemm_pipe(sB, 256, modW0, sW, 8, tid, r0, c0, a);
    {
        float4 b0a = *(const float4*)(modb0 + c0);
        float4 b0b = *(const float4*)(modb0 + c0 + 4);
        float bs0[8] = {b0a.x,b0a.y,b0a.z,b0a.w,b0b.x,b0b.y,b0b.z,b0b.w};
#pragma unroll
        for (int r = 0; r < 4; r++) {
            const float* h0p = &g_h0[(size_t)(hwb + r0 + r) * 256 + c0];
            float4 h0a = *(const float4*)h0p, h0b = *(const float4*)(h0p + 4);
            float h0v[8] = {h0a.x,h0a.y,h0a.z,h0a.w,h0b.x,h0b.y,h0b.z,h0b.w};
            float m0v[8];
#pragma unroll
            for (int c = 0; c < 4; c++) {
                float2 f = unpack2(a[r*4+c]);
                m0v[2*c]   = fmaxf(h0v[2*c]   + f.x + bs0[2*c],   0.f);
                m0v[2*c+1] = fmaxf(h0v[2*c+1] + f.y + bs0[2*c+1], 0.f);
            }
            *(float4*)&sA[(r0 + r) * 256 + c0]     = *(float4*)&m0v[0];
            *(float4*)&sA[(r0 + r) * 256 + c0 + 4] = *(float4*)&m0v[4];
        }
    }
    __syncthreads();

    // ---- stage 1b: x = m0 + relu(h1 + mod@modW1 + b)  -> sB (over mod) ----
#pragma unroll
    for (int i = 0; i < 16; i++) a[i] = 0ULL;
    gemm_pipe(sB, 256, modW1, sW, 8, tid, r0, c0, a);
    {
        float4 b1a = *(const float4*)(modb1 + c0);
        float4 b1b = *(const float4*)(modb1 + c0 + 4);
        float bs1[8] = {b1a.x,b1a.y,b1a.z,b1a.w,b1b.x,b1b.y,b1b.z,b1b.w};
        float xv[4][8];
#pragma unroll
        for (int r = 0; r < 4; r++) {
            const float* h1p = &g_h1[(size_t)(hwb + r0 + r) * 256 + c0];
            float4 h1a = *(const float4*)h1p, h1b = *(const float4*)(h1p + 4);
            float h1v[8] = {h1a.x,h1a.y,h1a.z,h1a.w,h1b.x,h1b.y,h1b.z,h1b.w};
            const float* m0p = &sA[(r0 + r) * 256 + c0];
#pragma unroll
            for (int c = 0; c < 4; c++) {
                float2 f = unpack2(a[r*4+c]);
                float v0 = fmaxf(h1v[2*c]   + f.x + bs1[2*c],   0.f);
                float v1 = fmaxf(h1v[2*c+1] + f.y + bs1[2*c+1], 0.f);
                xv[r][2*c]   = m0p[2*c]   + v0;
                xv[r][2*c+1] = m0p[2*c+1] + v1;
            }
        }
        __syncthreads();   // all reads of sB (mod) done before overwrite
#pragma unroll
        for (int r = 0; r < 4; r++) {
            *(float4*)&sB[(r0 + r) * 256 + c0]     = *(float4*)&xv[r][0];
            *(float4*)&sB[(r0 + r) * 256 + c0 + 4] = *(float4*)&xv[r][4];
        }
    }
    __syncthreads();

    // ---- stage 2: hv1 = relu(x @ hvW0 + b)  -> sB (over x) ----
#pragma unroll
    for (int i = 0; i < 16; i++) a[i] = 0ULL;
    gemm_pipe(sB, 256, hvW0, sW, 8, tid, r0, c0, a);
    {
        float4 bha = *(const float4*)(hvb0 + c0);
        float4 bhb = *(const float4*)(hvb0 + c0 + 4);
        float bh[8] = {bha.x,bha.y,bha.z,bha.w,bhb.x,bhb.y,bhb.z,bhb.w};
        float hv[4][8];
#pragma unroll
        for (int r = 0; r < 4; r++)
#pragma unroll
            for (int c = 0; c < 4; c++) {
                float2 f = unpack2(a[r*4+c]);
                hv[r][2*c]   = fmaxf(f.x + bh[2*c],   0.f);
                hv[r][2*c+1] = fmaxf(f.y + bh[2*c+1], 0.f);
            }
        __syncthreads();
#pragma unroll
        for (int r = 0; r < 4; r++) {
            *(float4*)&sB[(r0 + r) * 256 + c0]     = *(float4*)&hv[r][0];
            *(float4*)&sB[(r0 + r) * 256 + c0 + 4] = *(float4*)&hv[r][4];
        }
    }
    __syncthreads();

    // ---- stage 3: out = m0@outW0 + hv1@outW1 + biases ----
    {
#pragma unroll
        for (int rr = 0; rr < 4; rr++) {
            int r = r0 + rr;
            float p0 = 0.f, p1 = 0.f, p2 = 0.f;
            for (int k = lane; k < 256; k += 32) {
                float av = sA[r * 256 + k];
                float bv = sB[r * 256 + k];
                p0 += av * outW0[k * 3 + 0] + bv * outW1[k * 3 + 0];
                p1 += av * outW0[k * 3 + 1] + bv * outW1[k * 3 + 1];
                p2 += av * outW0[k * 3 + 2] + bv * outW1[k * 3 + 2];
            }
#pragma unroll
            for (int off = 16; off > 0; off >>= 1) {
                p0 += __shfl_down_sync(0xffffffffu, p0, off);
                p1 += __shfl_down_sync(0xffffffffu, p1, off);
                p2 += __shfl_down_sync(0xffffffffu, p2, off);
            }
            if (lane == 0) {
                size_t ro = (size_t)(base + r) * 3;
                out[ro + 0] = p0 + outb0[0] + outb1[0];
                out[ro + 1] = p1 + outb0[1] + outb1[1];
                out[ro + 2] = p2 + outb0[2] + outb1[2];
            }
        }
    }
}

// ============================================================================
extern "C" void kernel_launch(void* const* d_in, const int* in_sizes, int n_in,
                              void* d_out, int out_size)
{
    const float* coords = (const float*)d_in[0];
    const float* tokens = (const float*)d_in[1];
    const float* B_q    = (const float*)d_in[2];
    const float* B_l0   = (const float*)d_in[3];
    const float* B_l1   = (const float*)d_in[4];
    const float* qW     = (const float*)d_in[5];
    const float* qb     = (const float*)d_in[6];
    const float* toqW   = (const float*)d_in[7];
    const float* tokvW  = (const float*)d_in[8];
    const float* tooW   = (const float*)d_in[9];
    const float* toob   = (const float*)d_in[10];
    const float* bwW0   = (const float*)d_in[11];
    const float* bwb0   = (const float*)d_in[12];
    const float* bwW1   = (const float*)d_in[13];
    const float* bwb1   = (const float*)d_in[14];
    const float* modW0  = (const float*)d_in[15];
    const float* modb0  = (const float*)d_in[16];
    const float* modW1  = (const float*)d_in[17];
    const float* modb1  = (const float*)d_in[18];
    const float* hvW0   = (const float*)d_in[19];
    const float* hvb0   = (const float*)d_in[20];
    const float* outW0  = (const float*)d_in[21];
    const float* outb0  = (const float*)d_in[22];
    const float* outW1  = (const float*)d_in[23];
    const float* outb1  = (const float*)d_in[24];
    float* out = (float*)d_out;

    cudaFuncSetAttribute(k3_attn, cudaFuncAttributeMaxDynamicSharedMemorySize, 131072);
    cudaFuncSetAttribute(k5_v4,   cudaFuncAttributeMaxDynamicSharedMemorySize, 196608);

    k1_grid<<<HW / 16, 256>>>(coords, B_q, B_l0, B_l1, qW, qb, toqW,
                              bwW0, bwb0, bwW1, bwb1);
    k2_kv<<<dim3(MTOK / 16, BATCH), 256>>>(tokens, tokvW);
    k3_attn<<<dim3(HW / 256, 2, BATCH), 512, 131072>>>();
    k5_v4<<<(BATCH * HW) / 64, 512, 196608>>>(tooW, toob,
                                              modW0, modb0, modW1, modb1,
                                              hvW0, hvb0, outW0, outb0, outW1, outb1,
                                              out);
}

// round 5
// speedup vs baseline: 1.4680x; 1.4680x over previous
#include <cuda_runtime.h>
#include <math.h>

#define HW      16384
#define BATCH   4
#define MTOK    256
#define HD      256
#define INNER   128
#define DH      64

#define TWO_PI 6.2831853071795864769f

typedef unsigned long long u64;

// ---- packed f32x2 helpers (sm_100+) ---------------------------------------
__device__ __forceinline__ u64 pack1(float v) {
    u64 r; asm("mov.b64 %0, {%1, %2};" : "=l"(r) : "f"(v), "f"(v)); return r;
}
__device__ __forceinline__ u64 ffma2(u64 a, u64 b, u64 c) {
    u64 d; asm("fma.rn.f32x2 %0, %1, %2, %3;" : "=l"(d) : "l"(a), "l"(b), "l"(c)); return d;
}
__device__ __forceinline__ u64 fmul2(u64 a, u64 b) {
    u64 d; asm("mul.rn.f32x2 %0, %1, %2;" : "=l"(d) : "l"(a), "l"(b)); return d;
}
__device__ __forceinline__ u64 fadd2(u64 a, u64 b) {
    u64 d; asm("add.rn.f32x2 %0, %1, %2;" : "=l"(d) : "l"(a), "l"(b)); return d;
}
__device__ __forceinline__ float2 unpack2(u64 v) {
    float2 f; asm("mov.b64 {%0, %1}, %2;" : "=f"(f.x), "=f"(f.y) : "l"(v)); return f;
}

// ---- cp.async helpers ------------------------------------------------------
__device__ __forceinline__ void cpa16(float* dst, const float* src) {
    unsigned d = (unsigned)__cvta_generic_to_shared(dst);
    asm volatile("cp.async.ca.shared.global [%0], [%1], 16;" :: "r"(d), "l"(src));
}
#define CPA_COMMIT() asm volatile("cp.async.commit_group;" ::: "memory")
#define CPA_WAIT0()  asm volatile("cp.async.wait_group 0;"  ::: "memory")

// ---------------- scratch ---------------------------------------------------
__device__ float g_q  [HW * INNER];
__device__ float g_h0 [HW * HD];
__device__ float g_h1 [HW * HD];
__device__ float g_t  [HW];
__device__ float g_k  [BATCH * 2 * MTOK * DH];
__device__ float g_v  [BATCH * 2 * MTOK * DH];
__device__ float g_o  [BATCH * HW * INNER];

// ============================================================================
// K1: grid-shared features. 16 rows / block, 256 threads.
// ============================================================================
__global__ void k1_grid(const float* __restrict__ coords,
                        const float* __restrict__ Bq,
                        const float* __restrict__ Bl0,
                        const float* __restrict__ Bl1,
                        const float* __restrict__ qW,  const float* __restrict__ qb,
                        const float* __restrict__ toqW,
                        const float* __restrict__ bwW0, const float* __restrict__ bwb0,
                        const float* __restrict__ bwW1, const float* __restrict__ bwb1)
{
    __shared__ float four[3][16][64];
    __shared__ float xq[16][256];
    const int tid  = threadIdx.x;
    const int base = blockIdx.x * 16;

    for (int it = tid; it < 3 * 16 * 32; it += 256) {
        int mat = it >> 9;
        int rem = it & 511;
        int r   = rem >> 5;
        int i   = rem & 31;
        float x = coords[(base + r) * 2 + 0];
        float y = coords[(base + r) * 2 + 1];
        const float* Bm = (mat == 0) ? Bq : (mat == 1 ? Bl0 : Bl1);
        float proj = TWO_PI * (x * Bm[i * 2] + y * Bm[i * 2 + 1]);
        float s, c;
        sincosf(proj, &s, &c);
        four[mat][r][i]      = c;
        four[mat][r][i + 32] = s;
    }
    if (tid < 16) {
        float x = coords[(base + tid) * 2 + 0];
        float y = coords[(base + tid) * 2 + 1];
        int row = (int)(x * 16.0f); row = min(max(row, 0), 15);
        int col = (int)(y * 16.0f); col = min(max(col, 0), 15);
        g_t[base + tid] = (float)(row * 16 + col) * (1.0f / 256.0f);
    }
    __syncthreads();

    {
        const int j = tid;
        float acc[16];
#pragma unroll
        for (int r = 0; r < 16; r++) acc[r] = 0.f;
        for (int k = 0; k < 64; k++) {
            float w = qW[k * 256 + j];
#pragma unroll
            for (int r = 0; r < 16; r++) acc[r] = fmaf(four[0][r][k], w, acc[r]);
        }
        float b = qb[j];
#pragma unroll
        for (int r = 0; r < 16; r++) xq[r][j] = fmaxf(acc[r] + b, 0.f);
    }
    __syncthreads();

    {
        const int j    = tid & 127;
        const int half = tid >> 7;
        float acc[8];
#pragma unroll
        for (int r = 0; r < 8; r++) acc[r] = 0.f;
        for (int k = 0; k < 256; k++) {
            float w = toqW[k * 128 + j];
#pragma unroll
            for (int r = 0; r < 8; r++) acc[r] = fmaf(xq[half * 8 + r][k], w, acc[r]);
        }
#pragma unroll
        for (int r = 0; r < 8; r++) g_q[(base + half * 8 + r) * 128 + j] = acc[r];
    }

    {
        const int j = tid;
        float a0[16], a1[16];
#pragma unroll
        for (int r = 0; r < 16; r++) { a0[r] = 0.f; a1[r] = 0.f; }
        for (int k = 0; k < 64; k++) {
            float w0 = bwW0[k * 256 + j];
            float w1 = bwW1[k * 256 + j];
#pragma unroll
            for (int r = 0; r < 16; r++) {
                a0[r] = fmaf(four[1][r][k], w0, a0[r]);
                a1[r] = fmaf(four[2][r][k], w1, a1[r]);
            }
        }
        float b0 = bwb0[j], b1 = bwb1[j];
#pragma unroll
        for (int r = 0; r < 16; r++) {
            g_h0[(base + r) * 256 + j] = fmaxf(a0[r] + b0, 0.f);
            g_h1[(base + r) * 256 + j] = fmaxf(a1[r] + b1, 0.f);
        }
    }
}

// ============================================================================
// K2: kv = tokens @ tokvW -> per-head k / v.
// ============================================================================
__global__ void k2_kv(const float* __restrict__ tokens,
                      const float* __restrict__ tokvW)
{
    __shared__ float tok[16][256];
    const int tile = blockIdx.x;
    const int b    = blockIdx.y;
    const int tid  = threadIdx.x;

    const float* tb = tokens + (b * MTOK + tile * 16) * 256;
    for (int i = tid; i < 16 * 256; i += 256) tok[i >> 8][i & 255] = tb[i];
    __syncthreads();

    const int j = tid;
    float acc[16];
#pragma unroll
    for (int r = 0; r < 16; r++) acc[r] = 0.f;
    for (int k = 0; k < 256; k++) {
        float w = tokvW[k * 256 + j];
#pragma unroll
        for (int r = 0; r < 16; r++) acc[r] = fmaf(tok[r][k], w, acc[r]);
    }
#pragma unroll
    for (int r = 0; r < 16; r++) {
        int m = tile * 16 + r;
        if (j < 128) {
            int h = j >> 6, d = j & 63;
            g_k[((b * 2 + h) * MTOK + m) * DH + d] = acc[r];
        } else {
            int j2 = j - 128;
            int h = j2 >> 6, d = j2 & 63;
            g_v[((b * 2 + h) * MTOK + m) * DH + d] = acc[r];
        }
    }
}

// ============================================================================
// K3: attention with spatial bias. 256 threads/block, f32x2 math (R3 version).
// ============================================================================
__global__ void __launch_bounds__(256) k3_attn()
{
    extern __shared__ float sm[];
    float* ks = sm;
    float* vs = sm + MTOK * DH;

    const int h   = blockIdx.y;
    const int b   = blockIdx.z;
    const int tid = threadIdx.x;

    const float* kg = g_k + (b * 2 + h) * MTOK * DH;
    const float* vg = g_v + (b * 2 + h) * MTOK * DH;
    for (int i = tid * 4; i < MTOK * DH; i += 256 * 4) {
        *(float4*)&ks[i] = *(const float4*)&kg[i];
        *(float4*)&vs[i] = *(const float4*)&vg[i];
    }
    __syncthreads();

    const int row = blockIdx.x * 256 + tid;
    u64 q2[32];
    {
        const ulonglong2* qp = (const ulonglong2*)(g_q + row * 128 + h * 64);
#pragma unroll
        for (int i = 0; i < 16; i++) { ulonglong2 t = qp[i]; q2[2*i] = t.x; q2[2*i+1] = t.y; }
    }
    const float tt = g_t[row];

    u64 acc[32];
#pragma unroll
    for (int i = 0; i < 32; i++) acc[i] = 0ULL;
    float Mx = -1e30f, S = 0.f;

    for (int m = 0; m < 256; m++) {
        const ulonglong2* kp = (const ulonglong2*)&ks[m * 64];
        u64 sA = 0, sB = 0, sC = 0, sD = 0;
#pragma unroll
        for (int i = 0; i < 16; i += 2) {
            ulonglong2 k0 = kp[i];
            ulonglong2 k1 = kp[i + 1];
            sA = ffma2(q2[2*i    ], k0.x, sA);
            sB = ffma2(q2[2*i + 1], k0.y, sB);
            sC = ffma2(q2[2*i + 2], k1.x, sC);
            sD = ffma2(q2[2*i + 3], k1.y, sD);
        }
        float2 sf = unpack2(fadd2(fadd2(sA, sB), fadd2(sC, sD)));
        float pos  = ((float)m + 0.5f) * (1.0f / 256.0f);
        float diff = tt - pos;
        float s = (sf.x + sf.y) * 0.125f - 10.0f * diff * diff;

        if (s > Mx) {
            float corr = __expf(Mx - s);
            S *= corr;
            u64 cp = pack1(corr);
#pragma unroll
            for (int i = 0; i < 32; i++) acc[i] = fmul2(acc[i], cp);
            Mx = s;
        }
        float p = __expf(s - Mx);
        S += p;
        u64 pp = pack1(p);
        const ulonglong2* vp = (const ulonglong2*)&vs[m * 64];
#pragma unroll
        for (int i = 0; i < 16; i++) {
            ulonglong2 v0 = vp[i];
            acc[2*i    ] = ffma2(pp, v0.x, acc[2*i    ]);
            acc[2*i + 1] = ffma2(pp, v0.y, acc[2*i + 1]);
        }
    }

    float inv = 1.0f / S;
    float* og = g_o + ((size_t)b * HW + row) * 128 + h * 64;
#pragma unroll
    for (int i = 0; i < 32; i++) {
        float2 f = unpack2(acc[i]);
        float2 o2; o2.x = f.x * inv; o2.y = f.y * inv;
        *(float2*)&og[2 * i] = o2;
    }
}

// ============================================================================
// K5 v5: fused MLP chain. 32 rows/block, 128 threads (4 warps).
// 8 rows x 8 cols per thread; sequential GEMM passes (no dual accumulators).
// Weights via cp.async double buffer, 16-k chunks; 96 KB smem -> 2 CTAs/SM.
// ============================================================================
__device__ __forceinline__ void copy_chunk16(float* dst, const float* W, int k0, int tid)
{
#pragma unroll
    for (int it = 0; it < 8; it++) {
        int f  = it * 128 + tid;     // float4 id (1024 total = 16 rows x 64)
        int k  = f >> 6;
        int c4 = f & 63;
        cpa16(dst + k * 256 + c4 * 4, W + (k0 + k) * 256 + c4 * 4);
    }
}

// 16-k GEMM step: 8 rows x 8 cols per thread, k processed in pairs.
__device__ __forceinline__ void gemm16_8r(const float* sIn, int lda, int kbase,
                                          const float* wb, int r0, int c0, u64* a)
{
#pragma unroll
    for (int kk = 0; kk < 16; kk += 2) {
        const float* wr0 = wb + kk * 256;
        const float* wr1 = wb + (kk + 1) * 256;
        ulonglong2 wa = *(const ulonglong2*)(wr0 + c0);
        ulonglong2 wv = *(const ulonglong2*)(wr0 + c0 + 4);
        ulonglong2 xa = *(const ulonglong2*)(wr1 + c0);
        ulonglong2 xv = *(const ulonglong2*)(wr1 + c0 + 4);
#pragma unroll
        for (int r = 0; r < 8; r++) {
            float2 iv = *(const float2*)&sIn[(r0 + r) * lda + kbase + kk];
            u64 p0 = pack1(iv.x);
            u64 p1 = pack1(iv.y);
            a[r*4+0] = ffma2(p0, wa.x, a[r*4+0]);
            a[r*4+1] = ffma2(p0, wa.y, a[r*4+1]);
            a[r*4+2] = ffma2(p0, wv.x, a[r*4+2]);
            a[r*4+3] = ffma2(p0, wv.y, a[r*4+3]);
            a[r*4+0] = ffma2(p1, xa.x, a[r*4+0]);
            a[r*4+1] = ffma2(p1, xa.y, a[r*4+1]);
            a[r*4+2] = ffma2(p1, xv.x, a[r*4+2]);
            a[r*4+3] = ffma2(p1, xv.y, a[r*4+3]);
        }
    }
}

// full GEMM (K = nchunks*16), double-buffered weights
__device__ __forceinline__ void gemm_pipe(const float* sIn, int lda, const float* W,
                                          float* sW, int nchunks, int tid,
                                          int r0, int c0, u64* a)
{
    copy_chunk16(sW, W, 0, tid);
    CPA_COMMIT(); CPA_WAIT0();
    __syncthreads();
    for (int c = 0; c < nchunks; c++) {
        if (c < nchunks - 1) { copy_chunk16(sW + ((c+1)&1)*4096, W, (c+1)*16, tid); CPA_COMMIT(); }
        gemm16_8r(sIn, lda, c * 16, sW + (c&1)*4096, r0, c0, a);
        CPA_WAIT0();
        __syncthreads();
    }
}

__global__ void __launch_bounds__(128, 2) k5_v5(
    const float* __restrict__ tooW,  const float* __restrict__ toob,
    const float* __restrict__ modW0, const float* __restrict__ modb0,
    const float* __restrict__ modW1, const float* __restrict__ modb1,
    const float* __restrict__ hvW0,  const float* __restrict__ hvb0,
    const float* __restrict__ outW0, const float* __restrict__ outb0,
    const float* __restrict__ outW1, const float* __restrict__ outb1,
    float* __restrict__ out)
{
    extern __shared__ float smf[];
    float* sA = smf;              // 32x256 (o -> m0)
    float* sB = smf + 8192;       // 32x256 (mod -> x -> hv1)
    float* sW = smf + 16384;      // 2 x 4096 weight buffers (32 KB)

    const int tid  = threadIdx.x;
    const int warp = tid >> 5, lane = tid & 31;
    const int r0   = warp * 8;
    const int c0   = lane * 8;
    const int base = blockIdx.x * 32;
    const int hwb  = base & (HW - 1);

    // load o tile (32x128) into sA
    for (int i = tid * 4; i < 32 * 128; i += 512)
        *(float4*)&sA[i] = *(const float4*)&g_o[(size_t)base * 128 + i];
    __syncthreads();

    u64 a[32];

    // ---- stage 0: mod = o @ tooW + toob  -> sB ----
#pragma unroll
    for (int i = 0; i < 32; i++) a[i] = 0ULL;
    gemm_pipe(sA, 128, tooW, sW, 8, tid, r0, c0, a);
    {
        ulonglong2 ba = *(const ulonglong2*)(toob + c0);
        ulonglong2 bb = *(const ulonglong2*)(toob + c0 + 4);
#pragma unroll
        for (int r = 0; r < 8; r++) {
            ulonglong2 o1, o2;
            o1.x = fadd2(a[r*4+0], ba.x); o1.y = fadd2(a[r*4+1], ba.y);
            o2.x = fadd2(a[r*4+2], bb.x); o2.y = fadd2(a[r*4+3], bb.y);
            *(ulonglong2*)&sB[(r0 + r) * 256 + c0]     = o1;
            *(ulonglong2*)&sB[(r0 + r) * 256 + c0 + 4] = o2;
        }
    }
    __syncthreads();

    // ---- stage 1a: m0 = relu(h0 + mod@modW0 + b)  -> sA ----
#pragma unroll
    for (int i = 0; i < 32; i++) a[i] = 0ULL;
    gemm_pipe(sB, 256, modW0, sW, 16, tid, r0, c0, a);
    {
        float4 b0a = *(const float4*)(modb0 + c0);
        float4 b0b = *(const float4*)(modb0 + c0 + 4);
        float bs0[8] = {b0a.x,b0a.y,b0a.z,b0a.w,b0b.x,b0b.y,b0b.z,b0b.w};
#pragma unroll
        for (int r = 0; r < 8; r++) {
            const float* h0p = &g_h0[(size_t)(hwb + r0 + r) * 256 + c0];
            float4 h0a = *(const float4*)h0p, h0b = *(const float4*)(h0p + 4);
            float h0v[8] = {h0a.x,h0a.y,h0a.z,h0a.w,h0b.x,h0b.y,h0b.z,h0b.w};
            float m0v[8];
#pragma unroll
            for (int c = 0; c < 4; c++) {
                float2 f = unpack2(a[r*4+c]);
                m0v[2*c]   = fmaxf(h0v[2*c]   + f.x + bs0[2*c],   0.f);
                m0v[2*c+1] = fmaxf(h0v[2*c+1] + f.y + bs0[2*c+1], 0.f);
            }
            *(float4*)&sA[(r0 + r) * 256 + c0]     = *(float4*)&m0v[0];
            *(float4*)&sA[(r0 + r) * 256 + c0 + 4] = *(float4*)&m0v[4];
        }
    }
    __syncthreads();

    // ---- stage 1b: x = m0 + relu(h1 + mod@modW1 + b)  -> sB (over mod) ----
    // After gemm_pipe's final barrier every thread is done reading sB, so the
    // write-back below is safe without extra staging.
#pragma unroll
    for (int i = 0; i < 32; i++) a[i] = 0ULL;
    gemm_pipe(sB, 256, modW1, sW, 16, tid, r0, c0, a);
    {
        float4 b1a = *(const float4*)(modb1 + c0);
        float4 b1b = *(const float4*)(modb1 + c0 + 4);
        float bs1[8] = {b1a.x,b1a.y,b1a.z,b1a.w,b1b.x,b1b.y,b1b.z,b1b.w};
#pragma unroll
        for (int r = 0; r < 8; r++) {
            const float* h1p = &g_h1[(size_t)(hwb + r0 + r) * 256 + c0];
            float4 h1a = *(const float4*)h1p, h1b = *(const float4*)(h1p + 4);
            float h1v[8] = {h1a.x,h1a.y,h1a.z,h1a.w,h1b.x,h1b.y,h1b.z,h1b.w};
            const float* m0p = &sA[(r0 + r) * 256 + c0];
            float xv[8];
#pragma unroll
            for (int c = 0; c < 4; c++) {
                float2 f = unpack2(a[r*4+c]);
                float v0 = fmaxf(h1v[2*c]   + f.x + bs1[2*c],   0.f);
                float v1 = fmaxf(h1v[2*c+1] + f.y + bs1[2*c+1], 0.f);
                xv[2*c]   = m0p[2*c]   + v0;
                xv[2*c+1] = m0p[2*c+1] + v1;
            }
            *(float4*)&sB[(r0 + r) * 256 + c0]     = *(float4*)&xv[0];
            *(float4*)&sB[(r0 + r) * 256 + c0 + 4] = *(float4*)&xv[4];
        }
    }
    __syncthreads();

    // ---- stage 2: hv1 = relu(x @ hvW0 + b)  -> sB (over x) ----
#pragma unroll
    for (int i = 0; i < 32; i++) a[i] = 0ULL;
    gemm_pipe(sB, 256, hvW0, sW, 16, tid, r0, c0, a);
    {
        float4 bha = *(const float4*)(hvb0 + c0);
        float4 bhb = *(const float4*)(hvb0 + c0 + 4);
        float bh[8] = {bha.x,bha.y,bha.z,bha.w,bhb.x,bhb.y,bhb.z,bhb.w};
#pragma unroll
        for (int r = 0; r < 8; r++) {
            float hv[8];
#pragma unroll
            for (int c = 0; c < 4; c++) {
                float2 f = unpack2(a[r*4+c]);
                hv[2*c]   = fmaxf(f.x + bh[2*c],   0.f);
                hv[2*c+1] = fmaxf(f.y + bh[2*c+1], 0.f);
            }
            *(float4*)&sB[(r0 + r) * 256 + c0]     = *(float4*)&hv[0];
            *(float4*)&sB[(r0 + r) * 256 + c0 + 4] = *(float4*)&hv[4];
        }
    }
    __syncthreads();

    // ---- stage 3: out = m0@outW0 + hv1@outW1 + biases ----
    {
#pragma unroll
        for (int rr = 0; rr < 8; rr++) {
            int r = r0 + rr;
            float p0 = 0.f, p1 = 0.f, p2 = 0.f;
            for (int k = lane; k < 256; k += 32) {
                float av = sA[r * 256 + k];
                float bv = sB[r * 256 + k];
                p0 += av * outW0[k * 3 + 0] + bv * outW1[k * 3 + 0];
                p1 += av * outW0[k * 3 + 1] + bv * outW1[k * 3 + 1];
                p2 += av * outW0[k * 3 + 2] + bv * outW1[k * 3 + 2];
            }
#pragma unroll
            for (int off = 16; off > 0; off >>= 1) {
                p0 += __shfl_down_sync(0xffffffffu, p0, off);
                p1 += __shfl_down_sync(0xffffffffu, p1, off);
                p2 += __shfl_down_sync(0xffffffffu, p2, off);
            }
            if (lane == 0) {
                size_t ro = (size_t)(base + r) * 3;
                out[ro + 0] = p0 + outb0[0] + outb1[0];
                out[ro + 1] = p1 + outb0[1] + outb1[1];
                out[ro + 2] = p2 + outb0[2] + outb1[2];
            }
        }
    }
}

// ============================================================================
extern "C" void kernel_launch(void* const* d_in, const int* in_sizes, int n_in,
                              void* d_out, int out_size)
{
    const float* coords = (const float*)d_in[0];
    const float* tokens = (const float*)d_in[1];
    const float* B_q    = (const float*)d_in[2];
    const float* B_l0   = (const float*)d_in[3];
    const float* B_l1   = (const float*)d_in[4];
    const float* qW     = (const float*)d_in[5];
    const float* qb     = (const float*)d_in[6];
    const float* toqW   = (const float*)d_in[7];
    const float* tokvW  = (const float*)d_in[8];
    const float* tooW   = (const float*)d_in[9];
    const float* toob   = (const float*)d_in[10];
    const float* bwW0   = (const float*)d_in[11];
    const float* bwb0   = (const float*)d_in[12];
    const float* bwW1   = (const float*)d_in[13];
    const float* bwb1   = (const float*)d_in[14];
    const float* modW0  = (const float*)d_in[15];
    const float* modb0  = (const float*)d_in[16];
    const float* modW1  = (const float*)d_in[17];
    const float* modb1  = (const float*)d_in[18];
    const float* hvW0   = (const float*)d_in[19];
    const float* hvb0   = (const float*)d_in[20];
    const float* outW0  = (const float*)d_in[21];
    const float* outb0  = (const float*)d_in[22];
    const float* outW1  = (const float*)d_in[23];
    const float* outb1  = (const float*)d_in[24];
    float* out = (float*)d_out;

    cudaFuncSetAttribute(k3_attn, cudaFuncAttributeMaxDynamicSharedMemorySize, 131072);
    cudaFuncSetAttribute(k5_v5,   cudaFuncAttributeMaxDynamicSharedMemorySize, 98304);

    k1_grid<<<HW / 16, 256>>>(coords, B_q, B_l0, B_l1, qW, qb, toqW,
                              bwW0, bwb0, bwW1, bwb1);
    k2_kv<<<dim3(MTOK / 16, BATCH), 256>>>(tokens, tokvW);
    k3_attn<<<dim3(HW / 256, 2, BATCH), 256, 131072>>>();
    k5_v5<<<(BATCH * HW) / 32, 128, 98304>>>(tooW, toob,
                                             modW0, modb0, modW1, modb1,
                                             hvW0, hvb0, outW0, outb0, outW1, outb1,
                                             out);
}

// round 7
// speedup vs baseline: 2.0338x; 1.3855x over previous
#include <cuda_runtime.h>
#include <cuda_bf16.h>
#include <math.h>
#include <cstdint>

#define HW      16384
#define BATCH   4
#define MTOK    256
#define HD      256
#define INNER   128
#define DH      64

#define TWO_PI 6.2831853071795864769f

typedef unsigned long long u64;

// ---- packed f32x2 helpers (sm_100+) ---------------------------------------
__device__ __forceinline__ u64 pack1(float v) {
    u64 r; asm("mov.b64 %0, {%1, %2};" : "=l"(r) : "f"(v), "f"(v)); return r;
}
__device__ __forceinline__ u64 ffma2(u64 a, u64 b, u64 c) {
    u64 d; asm("fma.rn.f32x2 %0, %1, %2, %3;" : "=l"(d) : "l"(a), "l"(b), "l"(c)); return d;
}
__device__ __forceinline__ u64 fmul2(u64 a, u64 b) {
    u64 d; asm("mul.rn.f32x2 %0, %1, %2;" : "=l"(d) : "l"(a), "l"(b)); return d;
}
__device__ __forceinline__ u64 fadd2(u64 a, u64 b) {
    u64 d; asm("add.rn.f32x2 %0, %1, %2;" : "=l"(d) : "l"(a), "l"(b)); return d;
}
__device__ __forceinline__ float2 unpack2(u64 v) {
    float2 f; asm("mov.b64 {%0, %1}, %2;" : "=f"(f.x), "=f"(f.y) : "l"(v)); return f;
}

// ---- cp.async helpers ------------------------------------------------------
__device__ __forceinline__ void cpa16(void* dst, const void* src) {
    unsigned d = (unsigned)__cvta_generic_to_shared(dst);
    asm volatile("cp.async.ca.shared.global [%0], [%1], 16;" :: "r"(d), "l"(src));
}
#define CPA_COMMIT() asm volatile("cp.async.commit_group;" ::: "memory")
#define CPA_WAIT0()  asm volatile("cp.async.wait_group 0;"  ::: "memory")
#define CPA_WAIT1()  asm volatile("cp.async.wait_group 1;"  ::: "memory")

// ---- mma.sync / ldmatrix helpers (baseline PTX, sm_80+) --------------------
__device__ __forceinline__ uint32_t smem_to_u32(const void* p) {
    uint32_t a;
    asm("{ .reg .u64 t; cvta.to.shared.u64 t, %1; cvt.u32.u64 %0, t; }" : "=r"(a) : "l"(p));
    return a;
}
__device__ __forceinline__ void ldsm4(uint32_t* r, uint32_t addr) {
    asm volatile("ldmatrix.sync.aligned.m8n8.x4.shared.b16 {%0,%1,%2,%3}, [%4];"
        : "=r"(r[0]), "=r"(r[1]), "=r"(r[2]), "=r"(r[3]) : "r"(addr));
}
__device__ __forceinline__ void ldsm2(uint32_t* r, uint32_t addr) {
    asm volatile("ldmatrix.sync.aligned.m8n8.x2.shared.b16 {%0,%1}, [%2];"
        : "=r"(r[0]), "=r"(r[1]) : "r"(addr));
}
__device__ __forceinline__ void mma16816(float* d, const uint32_t* a, const uint32_t* b) {
    asm volatile("mma.sync.aligned.m16n8k16.row.col.f32.bf16.bf16.f32 "
        "{%0,%1,%2,%3}, {%4,%5,%6,%7}, {%8,%9}, {%0,%1,%2,%3};"
        : "+f"(d[0]), "+f"(d[1]), "+f"(d[2]), "+f"(d[3])
        : "r"(a[0]), "r"(a[1]), "r"(a[2]), "r"(a[3]), "r"(b[0]), "r"(b[1]));
}

__device__ __forceinline__ int swz(int b) { return b ^ ((b >> 3) & 0x70); }

__device__ __forceinline__ void split2(float v0, float v1, uint32_t& hi, uint32_t& lo) {
    __nv_bfloat16 h0 = __float2bfloat16(v0), h1 = __float2bfloat16(v1);
    float r0 = v0 - __bfloat162float(h0);
    float r1 = v1 - __bfloat162float(h1);
    __nv_bfloat16 l0 = __float2bfloat16(r0), l1 = __float2bfloat16(r1);
    hi = ((uint32_t)__bfloat16_as_ushort(h1) << 16) | __bfloat16_as_ushort(h0);
    lo = ((uint32_t)__bfloat16_as_ushort(l1) << 16) | __bfloat16_as_ushort(l0);
}
__device__ __forceinline__ float bfu(unsigned short u) {
    __nv_bfloat16_raw r; r.x = u;
    return __bfloat162float(__nv_bfloat16(r));
}

// ---------------- scratch ---------------------------------------------------
__device__ float g_q  [HW * INNER];
__device__ float g_h0 [HW * HD];
__device__ float g_h1 [HW * HD];
__device__ float g_t  [HW];
__device__ float g_k  [BATCH * 2 * MTOK * DH];
__device__ float g_v  [BATCH * 2 * MTOK * DH];
__device__ float g_o  [BATCH * HW * INNER];
// pre-split, pre-swizzled bf16 weight images:
// 14 k-chunks (tooW:2, modW0:4, modW1:4, hvW0:4) x 2 n-halves x 32KB (hi16K+lo16K)
__device__ __align__(128) uint8_t g_WB[14 * 2 * 32768];

// ============================================================================
// K0: prep weights -> split bf16 [n][k] chunk images with SW128 swizzle.
// ============================================================================
__global__ void k0_prepw(const float* __restrict__ tooW,
                         const float* __restrict__ modW0,
                         const float* __restrict__ modW1,
                         const float* __restrict__ hvW0)
{
    int m = blockIdx.y;           // matrix 0..3
    int k = blockIdx.x;           // 0..255
    int n = threadIdx.x;          // 0..255
    int Km = (m == 0) ? 128 : 256;
    if (k >= Km) return;
    const float* W = (m == 0) ? tooW : (m == 1) ? modW0 : (m == 2) ? modW1 : hvW0;
    float v = W[k * 256 + n];
    __nv_bfloat16 h = __float2bfloat16(v);
    float rres = v - __bfloat162float(h);
    __nv_bfloat16 l = __float2bfloat16(rres);
    const int mstart = (m == 0) ? 0 : (m == 1) ? 2 : (m == 2) ? 6 : 10;
    uint8_t* img = g_WB + ((size_t)(mstart + (k >> 6)) * 2 + (n >> 7)) * 32768;
    int b  = (n & 127) * 128 + (k & 63) * 2;
    int sw = swz(b);
    *(__nv_bfloat16*)(img + sw)         = h;
    *(__nv_bfloat16*)(img + 16384 + sw) = l;
}

// ============================================================================
// K1: grid-shared features. 16 rows / block, 256 threads.
// ============================================================================
__global__ void k1_grid(const float* __restrict__ coords,
                        const float* __restrict__ Bq,
                        const float* __restrict__ Bl0,
                        const float* __restrict__ Bl1,
                        const float* __restrict__ qW,  const float* __restrict__ qb,
                        const float* __restrict__ toqW,
                        const float* __restrict__ bwW0, const float* __restrict__ bwb0,
                        const float* __restrict__ bwW1, const float* __restrict__ bwb1)
{
    __shared__ float four[3][16][64];
    __shared__ float xq[16][256];
    const int tid  = threadIdx.x;
    const int base = blockIdx.x * 16;

    for (int it = tid; it < 3 * 16 * 32; it += 256) {
        int mat = it >> 9;
        int rem = it & 511;
        int r   = rem >> 5;
        int i   = rem & 31;
        float x = coords[(base + r) * 2 + 0];
        float y = coords[(base + r) * 2 + 1];
        const float* Bm = (mat == 0) ? Bq : (mat == 1 ? Bl0 : Bl1);
        float proj = TWO_PI * (x * Bm[i * 2] + y * Bm[i * 2 + 1]);
        float s, c;
        sincosf(proj, &s, &c);
        four[mat][r][i]      = c;
        four[mat][r][i + 32] = s;
    }
    if (tid < 16) {
        float x = coords[(base + tid) * 2 + 0];
        float y = coords[(base + tid) * 2 + 1];
        int row = (int)(x * 16.0f); row = min(max(row, 0), 15);
        int col = (int)(y * 16.0f); col = min(max(col, 0), 15);
        g_t[base + tid] = (float)(row * 16 + col) * (1.0f / 256.0f);
    }
    __syncthreads();

    {
        const int j = tid;
        float acc[16];
#pragma unroll
        for (int r = 0; r < 16; r++) acc[r] = 0.f;
        for (int k = 0; k < 64; k++) {
            float w = qW[k * 256 + j];
#pragma unroll
            for (int r = 0; r < 16; r++) acc[r] = fmaf(four[0][r][k], w, acc[r]);
        }
        float b = qb[j];
#pragma unroll
        for (int r = 0; r < 16; r++) xq[r][j] = fmaxf(acc[r] + b, 0.f);
    }
    __syncthreads();

    {
        const int j    = tid & 127;
        const int half = tid >> 7;
        float acc[8];
#pragma unroll
        for (int r = 0; r < 8; r++) acc[r] = 0.f;
        for (int k = 0; k < 256; k++) {
            float w = toqW[k * 128 + j];
#pragma unroll
            for (int r = 0; r < 8; r++) acc[r] = fmaf(xq[half * 8 + r][k], w, acc[r]);
        }
#pragma unroll
        for (int r = 0; r < 8; r++) g_q[(base + half * 8 + r) * 128 + j] = acc[r];
    }

    {
        const int j = tid;
        float a0[16], a1[16];
#pragma unroll
        for (int r = 0; r < 16; r++) { a0[r] = 0.f; a1[r] = 0.f; }
        for (int k = 0; k < 64; k++) {
            float w0 = bwW0[k * 256 + j];
            float w1 = bwW1[k * 256 + j];
#pragma unroll
            for (int r = 0; r < 16; r++) {
                a0[r] = fmaf(four[1][r][k], w0, a0[r]);
                a1[r] = fmaf(four[2][r][k], w1, a1[r]);
            }
        }
        float b0 = bwb0[j], b1 = bwb1[j];
#pragma unroll
        for (int r = 0; r < 16; r++) {
            g_h0[(base + r) * 256 + j] = fmaxf(a0[r] + b0, 0.f);
            g_h1[(base + r) * 256 + j] = fmaxf(a1[r] + b1, 0.f);
        }
    }
}

// ============================================================================
// K2: kv = tokens @ tokvW -> per-head k / v.
// ============================================================================
__global__ void k2_kv(const float* __restrict__ tokens,
                      const float* __restrict__ tokvW)
{
    __shared__ float tok[16][256];
    const int tile = blockIdx.x;
    const int b    = blockIdx.y;
    const int tid  = threadIdx.x;

    const float* tb = tokens + (b * MTOK + tile * 16) * 256;
    for (int i = tid; i < 16 * 256; i += 256) tok[i >> 8][i & 255] = tb[i];
    __syncthreads();

    const int j = tid;
    float acc[16];
#pragma unroll
    for (int r = 0; r < 16; r++) acc[r] = 0.f;
    for (int k = 0; k < 256; k++) {
        float w = tokvW[k * 256 + j];
#pragma unroll
        for (int r = 0; r < 16; r++) acc[r] = fmaf(tok[r][k], w, acc[r]);
    }
#pragma unroll
    for (int r = 0; r < 16; r++) {
        int m = tile * 16 + r;
        if (j < 128) {
            int h = j >> 6, d = j & 63;
            g_k[((b * 2 + h) * MTOK + m) * DH + d] = acc[r];
        } else {
            int j2 = j - 128;
            int h = j2 >> 6, d = j2 & 63;
            g_v[((b * 2 + h) * MTOK + m) * DH + d] = acc[r];
        }
    }
}

// ============================================================================
// K3: attention with spatial bias. 256 threads/block, f32x2 math.
// ============================================================================
__global__ void __launch_bounds__(256) k3_attn()
{
    extern __shared__ float sm[];
    float* ks = sm;
    float* vs = sm + MTOK * DH;

    const int h   = blockIdx.y;
    const int b   = blockIdx.z;
    const int tid = threadIdx.x;

    const float* kg = g_k + (b * 2 + h) * MTOK * DH;
    const float* vg = g_v + (b * 2 + h) * MTOK * DH;
    for (int i = tid * 4; i < MTOK * DH; i += 256 * 4) {
        *(float4*)&ks[i] = *(const float4*)&kg[i];
        *(float4*)&vs[i] = *(const float4*)&vg[i];
    }
    __syncthreads();

    const int row = blockIdx.x * 256 + tid;
    u64 q2[32];
    {
        const ulonglong2* qp = (const ulonglong2*)(g_q + row * 128 + h * 64);
#pragma unroll
        for (int i = 0; i < 16; i++) { ulonglong2 t = qp[i]; q2[2*i] = t.x; q2[2*i+1] = t.y; }
    }
    const float tt = g_t[row];

    u64 acc[32];
#pragma unroll
    for (int i = 0; i < 32; i++) acc[i] = 0ULL;
    float Mx = -1e30f, S = 0.f;

    for (int m = 0; m < 256; m++) {
        const ulonglong2* kp = (const ulonglong2*)&ks[m * 64];
        u64 sA = 0, sB = 0, sC = 0, sD = 0;
#pragma unroll
        for (int i = 0; i < 16; i += 2) {
            ulonglong2 k0 = kp[i];
            ulonglong2 k1 = kp[i + 1];
            sA = ffma2(q2[2*i    ], k0.x, sA);
            sB = ffma2(q2[2*i + 1], k0.y, sB);
            sC = ffma2(q2[2*i + 2], k1.x, sC);
            sD = ffma2(q2[2*i + 3], k1.y, sD);
        }
        float2 sf = unpack2(fadd2(fadd2(sA, sB), fadd2(sC, sD)));
        float pos  = ((float)m + 0.5f) * (1.0f / 256.0f);
        float diff = tt - pos;
        float s = (sf.x + sf.y) * 0.125f - 10.0f * diff * diff;

        if (s > Mx) {
            float corr = __expf(Mx - s);
            S *= corr;
            u64 cp = pack1(corr);
#pragma unroll
            for (int i = 0; i < 32; i++) acc[i] = fmul2(acc[i], cp);
            Mx = s;
        }
        float p = __expf(s - Mx);
        S += p;
        u64 pp = pack1(p);
        const ulonglong2* vp = (const ulonglong2*)&vs[m * 64];
#pragma unroll
        for (int i = 0; i < 16; i++) {
            ulonglong2 v0 = vp[i];
            acc[2*i    ] = ffma2(pp, v0.x, acc[2*i    ]);
            acc[2*i + 1] = ffma2(pp, v0.y, acc[2*i + 1]);
        }
    }

    float inv = 1.0f / S;
    float* og = g_o + ((size_t)b * HW + row) * 128 + h * 64;
#pragma unroll
    for (int i = 0; i < 32; i++) {
        float2 f = unpack2(acc[i]);
        float2 o2; o2.x = f.x * inv; o2.y = f.y * inv;
        *(float2*)&og[2 * i] = o2;
    }
}

// ============================================================================
// K5 mma.sync: fused MLP chain via split-bf16 tensor-core GEMMs.
// CTA = 64 rows, 256 threads (8 warps = 2M x 4N). Warp tile 32x32 per N-pass.
// Stages: mod = o@tooW ; m0 = relu(h0+mod@modW0+b) ; x = m0+relu(h1+mod@modW1+b)
//         hv1 = relu(x@hvW0+b). Output projections folded into epilogues.
// ============================================================================
// smem layout (bytes)
#define SMB_MOD   0          // A buffer: mod (hi 32K @0, lo 32K @32768)
#define SMB_X     65536      // A buffer: o, then m0/x
#define SMB_B     131072     // 2 x 32KB B chunk buffers (hi 16K + lo 16K each)
#define SMB_CONST 196608     // toob|modb0|modb1|hvb0|OW0|OW1 (2560 floats)
#define SMB_PSM   206848     // 64 x 3 fp32 projection accum
#define SMB_TOTAL 207616

// one GEMM pass: acc[2][4][4] fp32, A at Aoff (hi; lo at +32768), weights
// streamed from g_WB chunk images [mstart .. mstart+nch), n-half = pass.
__device__ __forceinline__ void run_gemm(char* smem, uint32_t sb, int Aoff,
                                         int mstart, int nch, int pass,
                                         int m0w, int n0p, int tid, int l,
                                         float* acc)
{
    // prologue: chunk 0
    {
        const uint8_t* src = g_WB + ((size_t)mstart * 2 + pass) * 32768;
        char* dst = smem + SMB_B;
#pragma unroll
        for (int it = 0; it < 8; it++) {
            int i = (it * 256 + tid) * 16;
            cpa16(dst + i, src + i);
        }
        CPA_COMMIT();
    }
    for (int c = 0; c < nch; c++) {
        if (c + 1 < nch) {
            const uint8_t* src = g_WB + ((size_t)(mstart + c + 1) * 2 + pass) * 32768;
            char* dst = smem + SMB_B + ((c + 1) & 1) * 32768;
#pragma unroll
            for (int it = 0; it < 8; it++) {
                int i = (it * 256 + tid) * 16;
                cpa16(dst + i, src + i);
            }
            CPA_COMMIT();
            CPA_WAIT1();
        } else {
            CPA_WAIT0();
        }
        __syncthreads();

        const uint32_t bB   = sb + SMB_B + (c & 1) * 32768;
        const uint32_t bAhi = sb + Aoff + c * 8192;
        const uint32_t bAlo = bAhi + 32768;

#pragma unroll
        for (int t4 = 0; t4 < 4; t4++) {
            uint32_t ahi[2][4], alo[2][4];
            const int arow = l & 15;
            const int akb  = t4 * 32 + (l >> 4) * 16;
#pragma unroll
            for (int mt = 0; mt < 2; mt++) {
                int ab = (m0w + mt * 16 + arow) * 128 + akb;
                int sw = swz(ab);
                ldsm4(ahi[mt], bAhi + sw);
                ldsm4(alo[mt], bAlo + sw);
            }
#pragma unroll
            for (int nt = 0; nt < 4; nt++) {
                const int nrow = n0p + nt * 8 + (l & 7);
                int bb = nrow * 128 + t4 * 32 + ((l >> 3) & 1) * 16;
                int sw = swz(bb);
                uint32_t bhi[2], blo[2];
                ldsm2(bhi, bB + sw);
                ldsm2(blo, bB + 16384 + sw);
                float* a0 = acc + (0 * 4 + nt) * 4;
                float* a1 = acc + (1 * 4 + nt) * 4;
                mma16816(a0, ahi[0], bhi);
                mma16816(a1, ahi[1], bhi);
                mma16816(a0, ahi[0], blo);
                mma16816(a1, ahi[1], blo);
                mma16816(a0, alo[0], bhi);
                mma16816(a1, alo[1], bhi);
            }
        }
        __syncthreads();
    }
}

__global__ void __launch_bounds__(256, 1) k5_mma(
    const float* __restrict__ toob,
    const float* __restrict__ modb0, const float* __restrict__ modb1,
    const float* __restrict__ hvb0,
    const float* __restrict__ outW0, const float* __restrict__ outb0,
    const float* __restrict__ outW1, const float* __restrict__ outb1,
    float* __restrict__ out)
{
    extern __shared__ char smem[];
    const uint32_t sb = smem_to_u32(smem);
    const int tid  = threadIdx.x;
    const int w    = tid >> 5;
    const int l    = tid & 31;
    const int m0w  = 32 * (w & 1);        // warp row base (0 or 32)
    const int n0p  = 32 * (w >> 1);       // warp col base within 128-wide pass
    const int base = blockIdx.x * 64;     // global row base
    const int hb   = base & (HW - 1);     // row base into g_h0/g_h1

    float* sC    = (float*)(smem + SMB_CONST);
    float* sToob = sC;
    float* sMb0  = sC + 256;
    float* sMb1  = sC + 512;
    float* sHvb  = sC + 768;
    float* sOW0  = sC + 1024;
    float* sOW1  = sC + 1792;
    float* pSM   = (float*)(smem + SMB_PSM);

    for (int i = tid; i < 256; i += 256) {
        sToob[i] = toob[i];
        sMb0[i]  = modb0[i];
        sMb1[i]  = modb1[i];
        sHvb[i]  = hvb0[i];
    }
    for (int i = tid; i < 768; i += 256) {
        sOW0[i] = outW0[i];
        sOW1[i] = outW1[i];
    }
    for (int i = tid; i < 192; i += 256) pSM[i] = 0.f;

    // ---- load o (64x128 fp32) -> split bf16 chunks 0,1 of SMB_X ----
    for (int i = tid; i < 64 * 64; i += 256) {
        int r  = i >> 6;
        int kp = i & 63;
        int k  = kp * 2;
        float2 v = *(const float2*)&g_o[((size_t)(base + r)) * 128 + k];
        uint32_t hi, lo;
        split2(v.x, v.y, hi, lo);
        int kc = k >> 6;
        int b  = r * 128 + (k & 63) * 2;
        int sw = swz(b);
        *(uint32_t*)(smem + SMB_X + kc * 8192 + sw)         = hi;
        *(uint32_t*)(smem + SMB_X + 32768 + kc * 8192 + sw) = lo;
    }
    __syncthreads();

    float acc[32];
    float p[12];
#pragma unroll
    for (int i = 0; i < 12; i++) p[i] = 0.f;

    // ================= stage 0: mod = o @ tooW + toob -> SMB_MOD =============
#pragma unroll 1
    for (int pass = 0; pass < 2; pass++) {
#pragma unroll
        for (int i = 0; i < 32; i++) acc[i] = 0.f;
        run_gemm(smem, sb, SMB_X, 0, 2, pass, m0w, n0p, tid, l, acc);
#pragma unroll
        for (int mt = 0; mt < 2; mt++)
#pragma unroll
        for (int nt = 0; nt < 4; nt++) {
            float* a = acc + (mt * 4 + nt) * 4;
            int c0 = pass * 128 + n0p + nt * 8 + (l & 3) * 2;
            int rA = m0w + mt * 16 + (l >> 2);
            float b0 = sToob[c0], b1 = sToob[c0 + 1];
            int kc = c0 >> 6;
            int bby = (c0 & 63) * 2;
            uint32_t hi, lo;
            split2(a[0] + b0, a[1] + b1, hi, lo);
            int sw = swz(rA * 128 + bby);
            *(uint32_t*)(smem + SMB_MOD + kc * 8192 + sw)         = hi;
            *(uint32_t*)(smem + SMB_MOD + 32768 + kc * 8192 + sw) = lo;
            split2(a[2] + b0, a[3] + b1, hi, lo);
            sw = swz((rA + 8) * 128 + bby);
            *(uint32_t*)(smem + SMB_MOD + kc * 8192 + sw)         = hi;
            *(uint32_t*)(smem + SMB_MOD + 32768 + kc * 8192 + sw) = lo;
        }
    }
    __syncthreads();

    // ================= stage 1: m0 = relu(h0 + mod@modW0 + b) -> SMB_X =======
#pragma unroll 1
    for (int pass = 0; pass < 2; pass++) {
#pragma unroll
        for (int i = 0; i < 32; i++) acc[i] = 0.f;
        run_gemm(smem, sb, SMB_MOD, 2, 4, pass, m0w, n0p, tid, l, acc);
#pragma unroll
        for (int mt = 0; mt < 2; mt++)
#pragma unroll
        for (int nt = 0; nt < 4; nt++) {
            float* a = acc + (mt * 4 + nt) * 4;
            int c0 = pass * 128 + n0p + nt * 8 + (l & 3) * 2;
            int rA = m0w + mt * 16 + (l >> 2);
            float b0 = sMb0[c0], b1 = sMb0[c0 + 1];
            int kc = c0 >> 6;
            int bby = (c0 & 63) * 2;
#pragma unroll
            for (int half = 0; half < 2; half++) {
                int r = rA + half * 8;
                float2 h0 = *(const float2*)&g_h0[((size_t)(hb + r)) * 256 + c0];
                float v0 = fmaxf(h0.x + a[half * 2 + 0] + b0, 0.f);
                float v1 = fmaxf(h0.y + a[half * 2 + 1] + b1, 0.f);
                int slot = mt * 2 + half;
                p[slot * 3 + 0] = fmaf(v0, sOW0[c0 * 3 + 0], fmaf(v1, sOW0[c0 * 3 + 3], p[slot * 3 + 0]));
                p[slot * 3 + 1] = fmaf(v0, sOW0[c0 * 3 + 1], fmaf(v1, sOW0[c0 * 3 + 4], p[slot * 3 + 1]));
                p[slot * 3 + 2] = fmaf(v0, sOW0[c0 * 3 + 2], fmaf(v1, sOW0[c0 * 3 + 5], p[slot * 3 + 2]));
                uint32_t hi, lo;
                split2(v0, v1, hi, lo);
                int sw = swz(r * 128 + bby);
                *(uint32_t*)(smem + SMB_X + kc * 8192 + sw)         = hi;
                *(uint32_t*)(smem + SMB_X + 32768 + kc * 8192 + sw) = lo;
            }
        }
    }
    __syncthreads();

    // ================= stage 2: x = m0 + relu(h1 + mod@modW1 + b) -> SMB_X ===
#pragma unroll 1
    for (int pass = 0; pass < 2; pass++) {
#pragma unroll
        for (int i = 0; i < 32; i++) acc[i] = 0.f;
        run_gemm(smem, sb, SMB_MOD, 6, 4, pass, m0w, n0p, tid, l, acc);
#pragma unroll
        for (int mt = 0; mt < 2; mt++)
#pragma unroll
        for (int nt = 0; nt < 4; nt++) {
            float* a = acc + (mt * 4 + nt) * 4;
            int c0 = pass * 128 + n0p + nt * 8 + (l & 3) * 2;
            int rA = m0w + mt * 16 + (l >> 2);
            float b0 = sMb1[c0], b1 = sMb1[c0 + 1];
            int kc = c0 >> 6;
            int bby = (c0 & 63) * 2;
#pragma unroll
            for (int half = 0; half < 2; half++) {
                int r = rA + half * 8;
                float2 h1 = *(const float2*)&g_h1[((size_t)(hb + r)) * 256 + c0];
                float m10 = fmaxf(h1.x + a[half * 2 + 0] + b0, 0.f);
                float m11 = fmaxf(h1.y + a[half * 2 + 1] + b1, 0.f);
                int sw = swz(r * 128 + bby);
                uint32_t mh = *(uint32_t*)(smem + SMB_X + kc * 8192 + sw);
                uint32_t ml = *(uint32_t*)(smem + SMB_X + 32768 + kc * 8192 + sw);
                float x0 = bfu((unsigned short)(mh & 0xffff)) + bfu((unsigned short)(ml & 0xffff)) + m10;
                float x1 = bfu((unsigned short)(mh >> 16))    + bfu((unsigned short)(ml >> 16))    + m11;
                uint32_t hi, lo;
                split2(x0, x1, hi, lo);
                *(uint32_t*)(smem + SMB_X + kc * 8192 + sw)         = hi;
                *(uint32_t*)(smem + SMB_X + 32768 + kc * 8192 + sw) = lo;
            }
        }
    }
    __syncthreads();

    // ================= stage 3: hv1 = relu(x@hvW0 + b); project ===============
#pragma unroll 1
    for (int pass = 0; pass < 2; pass++) {
#pragma unroll
        for (int i = 0; i < 32; i++) acc[i] = 0.f;
        run_gemm(smem, sb, SMB_X, 10, 4, pass, m0w, n0p, tid, l, acc);
#pragma unroll
        for (int mt = 0; mt < 2; mt++)
#pragma unroll
        for (int nt = 0; nt < 4; nt++) {
            float* a = acc + (mt * 4 + nt) * 4;
            int c0 = pass * 128 + n0p + nt * 8 + (l & 3) * 2;
            float b0 = sHvb[c0], b1 = sHvb[c0 + 1];
#pragma unroll
            for (int half = 0; half < 2; half++) {
                float v0 = fmaxf(a[half * 2 + 0] + b0, 0.f);
                float v1 = fmaxf(a[half * 2 + 1] + b1, 0.f);
                int slot = mt * 2 + half;
                p[slot * 3 + 0] = fmaf(v0, sOW1[c0 * 3 + 0], fmaf(v1, sOW1[c0 * 3 + 3], p[slot * 3 + 0]));
                p[slot * 3 + 1] = fmaf(v0, sOW1[c0 * 3 + 1], fmaf(v1, sOW1[c0 * 3 + 4], p[slot * 3 + 1]));
                p[slot * 3 + 2] = fmaf(v0, sOW1[c0 * 3 + 2], fmaf(v1, sOW1[c0 * 3 + 5], p[slot * 3 + 2]));
            }
        }
    }

    // ---- reduce projections: quad shfl, then smem atomics ----
#pragma unroll
    for (int slot = 0; slot < 4; slot++) {
        int r = m0w + (slot >> 1) * 16 + (l >> 2) + (slot & 1) * 8;
#pragma unroll
        for (int j = 0; j < 3; j++) {
            float v = p[slot * 3 + j];
            v += __shfl_xor_sync(0xffffffffu, v, 1);
            v += __shfl_xor_sync(0xffffffffu, v, 2);
            if ((l & 3) == 0) atomicAdd(&pSM[r * 3 + j], v);
        }
    }
    __syncthreads();

    for (int i = tid; i < 192; i += 256) {
        int r = i / 3, j = i - r * 3;
        out[((size_t)(base + r)) * 3 + j] = pSM[i] + outb0[j] + outb1[j];
    }
}

// ============================================================================
extern "C" void kernel_launch(void* const* d_in, const int* in_sizes, int n_in,
                              void* d_out, int out_size)
{
    const float* coords = (const float*)d_in[0];
    const float* tokens = (const float*)d_in[1];
    const float* B_q    = (const float*)d_in[2];
    const float* B_l0   = (const float*)d_in[3];
    const float* B_l1   = (const float*)d_in[4];
    const float* qW     = (const float*)d_in[5];
    const float* qb     = (const float*)d_in[6];
    const float* toqW   = (const float*)d_in[7];
    const float* tokvW  = (const float*)d_in[8];
    const float* tooW   = (const float*)d_in[9];
    const float* toob   = (const float*)d_in[10];
    const float* bwW0   = (const float*)d_in[11];
    const float* bwb0   = (const float*)d_in[12];
    const float* bwW1   = (const float*)d_in[13];
    const float* bwb1   = (const float*)d_in[14];
    const float* modW0  = (const float*)d_in[15];
    const float* modb0  = (const float*)d_in[16];
    const float* modW1  = (const float*)d_in[17];
    const float* modb1  = (const float*)d_in[18];
    const float* hvW0   = (const float*)d_in[19];
    const float* hvb0   = (const float*)d_in[20];
    const float* outW0  = (const float*)d_in[21];
    const float* outb0  = (const float*)d_in[22];
    const float* outW1  = (const float*)d_in[23];
    const float* outb1  = (const float*)d_in[24];
    float* out = (float*)d_out;

    cudaFuncSetAttribute(k3_attn, cudaFuncAttributeMaxDynamicSharedMemorySize, 131072);
    cudaFuncSetAttribute(k5_mma,  cudaFuncAttributeMaxDynamicSharedMemorySize, SMB_TOTAL);

    k0_prepw<<<dim3(256, 4), 256>>>(tooW, modW0, modW1, hvW0);
    k1_grid<<<HW / 16, 256>>>(coords, B_q, B_l0, B_l1, qW, qb, toqW,
                              bwW0, bwb0, bwW1, bwb1);
    k2_kv<<<dim3(MTOK / 16, BATCH), 256>>>(tokens, tokvW);
    k3_attn<<<dim3(HW / 256, 2, BATCH), 256, 131072>>>();
    k5_mma<<<(BATCH * HW) / 64, 256, SMB_TOTAL>>>(toob, modb0, modb1, hvb0,
                                                  outW0, outb0, outW1, outb1,
                                                  out);
}